// round 3
// baseline (speedup 1.0000x reference)
#include <cuda_runtime.h>
#include <cstdint>

#define BATCH 131072
#define FEAT  32
#define DEG   16
#define CLS   64
#define GRIDK 8
#define TB    256      // batch rows per block
#define YSTR  260      // padded y_sh row stride

__global__ __launch_bounds__(256)
void qkan_lit_kernel(const float* __restrict__ X,
                     const float* __restrict__ phases,
                     const float* __restrict__ lcu_w,
                     const float* __restrict__ cand0,   // one of sum_scale/sum_bias
                     const float* __restrict__ cand1,   // the other
                     const float* __restrict__ kan_coeff,
                     const float* __restrict__ kan_bias,
                     float* __restrict__ out) {
    extern __shared__ float smem[];
    float* coeff_sh = smem;                 // [f][k][c] : 16384
    float* y_sh     = smem + 16384;         // [f][row(pad)] : 32*260 = 8320
    float* w_sh     = y_sh + 32 * YSTR;     // [f][d] : 512
    float* inv_sh   = w_sh + 512;           // 32
    float* ph_sh    = inv_sh + 32;          // 16
    float* sc_sh    = ph_sh + 16;           // 32
    float* bi_sh    = sc_sh + 32;           // 32
    float* kb_sh    = bi_sh + 32;           // 64
    __shared__ int flag_sh;                 // 1 if cand0 is sum_scale

    const int t  = threadIdx.x;
    const int b0 = blockIdx.x * TB;
    const float CLIPF = (float)(1.0 - 1e-6);

    // ---- disambiguate sum_scale (mean ~1) vs sum_bias (mean ~0) by data ----
    if (t == 0) {
        float s0 = 0.f, s1 = 0.f;
        for (int i = 0; i < 32; i++) { s0 += cand0[i]; s1 += cand1[i]; }
        flag_sh = (s0 > s1) ? 1 : 0;
    }
    __syncthreads();

    // ---- staging ----
    for (int j = t; j < 512; j += 256) w_sh[j] = lcu_w[j];      // [f][d], f*16+d
    if (t < 32) {
        float denom = 1e-6f;
#pragma unroll
        for (int d = 0; d < DEG; d++) denom += fabsf(lcu_w[t * DEG + d]);
        inv_sh[t] = 1.0f / denom;
        sc_sh[t] = flag_sh ? cand0[t] : cand1[t];
        bi_sh[t] = flag_sh ? cand1[t] : cand0[t];
    }
    if (t < 16) ph_sh[t] = phases[t];
    if (t < 64) kb_sh[t] = kan_bias[t];
    // kan_coeff global [c][f][k] (shape C,F,K) -> shared [f][k][c]
    for (int j = t; j < CLS * FEAT * GRIDK; j += 256) {
        const int c   = j >> 8;             // class
        const int rem = j & 255;            // f*8 + k
        coeff_sh[rem * 64 + c] = kan_coeff[j];
    }
    __syncthreads();

    // ---- Phase A: LITERAL stage 1: theta=acos(clip(x)); qsvt_d = cos(k*theta + phi_d) ----
    {
        const int f  = t & 31;
        const int w8 = t >> 5;
        const float invd = inv_sh[f];
        const float sc = sc_sh[f];
        const float bi = bi_sh[f];
        for (int i = 0; i < TB / 8; i++) {
            const int r = w8 + 8 * i;
            float x = X[(size_t)(b0 + r) * FEAT + f];
            x = fminf(fmaxf(x, -CLIPF), CLIPF);
            const float theta = acosf(x);
            float num = 0.f;
#pragma unroll
            for (int d = 0; d < DEG; d++) {
                const float q = cosf(fmaf((float)(d + 1), theta, ph_sh[d]));
                num = fmaf(w_sh[f * DEG + d], q, num);
            }
            const float lcu = num * invd;
            const float y = tanhf(fmaf(sc, lcu, bi));
            y_sh[f * YSTR + r] = y;
        }
    }
    __syncthreads();

    // ---- Phase B: LITERAL stage 2: t2=acos(clip(y)); basis_k = cos(k*t2); GEMM ----
    // One thread per batch row; all 64 classes accumulated in registers.
    {
        float acc[CLS];
#pragma unroll
        for (int c = 0; c < CLS; c++) acc[c] = 0.f;

        for (int f = 0; f < FEAT; f++) {
            float y = y_sh[f * YSTR + t];
            y = fminf(fmaxf(y, -CLIPF), CLIPF);
            const float t2 = acosf(y);
            float basis[GRIDK];
            basis[0] = 1.0f;
#pragma unroll
            for (int k = 1; k < GRIDK; k++) basis[k] = cosf((float)k * t2);

            const float* cp = coeff_sh + f * (GRIDK * CLS);
#pragma unroll
            for (int k = 0; k < GRIDK; k++) {
                const float bk = basis[k];
                const float4* q = (const float4*)(cp + k * CLS);
#pragma unroll
                for (int c4 = 0; c4 < 16; c4++) {
                    const float4 v = q[c4];
                    acc[c4 * 4 + 0] = fmaf(bk, v.x, acc[c4 * 4 + 0]);
                    acc[c4 * 4 + 1] = fmaf(bk, v.y, acc[c4 * 4 + 1]);
                    acc[c4 * 4 + 2] = fmaf(bk, v.z, acc[c4 * 4 + 2]);
                    acc[c4 * 4 + 3] = fmaf(bk, v.w, acc[c4 * 4 + 3]);
                }
            }
        }

        // epilogue: + kan_bias, contiguous 256B store per thread
        const size_t row = (size_t)(b0 + t);
        float4* op = (float4*)(out + row * CLS);
#pragma unroll
        for (int c4 = 0; c4 < 16; c4++) {
            float4 v;
            v.x = acc[c4 * 4 + 0] + kb_sh[c4 * 4 + 0];
            v.y = acc[c4 * 4 + 1] + kb_sh[c4 * 4 + 1];
            v.z = acc[c4 * 4 + 2] + kb_sh[c4 * 4 + 2];
            v.w = acc[c4 * 4 + 3] + kb_sh[c4 * 4 + 3];
            op[c4] = v;
        }
    }
}

extern "C" void kernel_launch(void* const* d_in, const int* in_sizes, int n_in,
                              void* d_out, int out_size) {
    // Identify inputs by element count; sizes are unique except the two 32-vectors,
    // which the kernel disambiguates at runtime by their means.
    int iX = 0, iP = 1, iW = 2, iC = 5, iKB = 6;
    int i32[2] = {3, 4};
    int n32 = 0;
    for (int i = 0; i < n_in; i++) {
        switch (in_sizes[i]) {
            case 4194304: iX = i; break;
            case 16:      iP = i; break;
            case 512:     iW = i; break;
            case 16384:   iC = i; break;
            case 64:      iKB = i; break;
            case 32:      if (n32 < 2) i32[n32] = i; n32++; break;
            default: break;
        }
    }

    const float* X      = (const float*)d_in[iX];
    const float* phases = (const float*)d_in[iP];
    const float* w      = (const float*)d_in[iW];
    const float* cand0  = (const float*)d_in[i32[0]];
    const float* cand1  = (const float*)d_in[i32[1]];
    const float* coeff  = (const float*)d_in[iC];
    const float* kbias  = (const float*)d_in[iKB];
    float* out          = (float*)d_out;

    const size_t smem_bytes =
        (16384 + 32 * YSTR + 512 + 32 + 16 + 32 + 32 + 64) * sizeof(float);  // 101568 B
    cudaFuncSetAttribute(qkan_lit_kernel, cudaFuncAttributeMaxDynamicSharedMemorySize,
                         (int)smem_bytes);

    qkan_lit_kernel<<<BATCH / TB, 256, smem_bytes>>>(X, phases, w, cand0, cand1,
                                                     coeff, kbias, out);
}

// round 4
// speedup vs baseline: 2.0958x; 2.0958x over previous
#include <cuda_runtime.h>
#include <cstdint>

#define BATCH 131072
#define FEAT  32
#define DEG   16
#define CLS   64
#define GRIDK 8
#define TB    256      // batch rows per block
#define YSTR  258      // even stride: float2 y reads stay 8B-aligned

__device__ __forceinline__ unsigned long long fma2(unsigned long long a,
                                                   unsigned long long b,
                                                   unsigned long long c) {
    unsigned long long d;
    asm("fma.rn.f32x2 %0, %1, %2, %3;" : "=l"(d) : "l"(a), "l"(b), "l"(c));
    return d;
}
__device__ __forceinline__ unsigned long long add2(unsigned long long a,
                                                   unsigned long long b) {
    unsigned long long d;
    asm("add.rn.f32x2 %0, %1, %2;" : "=l"(d) : "l"(a), "l"(b));
    return d;
}
__device__ __forceinline__ unsigned long long pack2(float v) {
    unsigned int u = __float_as_uint(v);
    unsigned long long d;
    asm("mov.b64 %0, {%1, %1};" : "=l"(d) : "r"(u));
    return d;
}

__global__ __launch_bounds__(256, 2)
void qkan_kernel(const float* __restrict__ X,
                 const float* __restrict__ phases,
                 const float* __restrict__ lcu_w,
                 const float* __restrict__ cand0,   // one of sum_scale/sum_bias
                 const float* __restrict__ cand1,   // the other
                 const float* __restrict__ kan_coeff,
                 const float* __restrict__ kan_bias,
                 float* __restrict__ out) {
    extern __shared__ float smem[];
    float* coeff_sh = smem;                  // [f][k][c] : 16384
    float* y_sh     = smem + 16384;          // [f][row]  : 32*258 = 8256
    float* wT_sh    = y_sh + 32 * YSTR;      // [d][f]    : 512
    float* inv_sh   = wT_sh + 512;           // 32
    float* cp_sh    = inv_sh + 32;           // 16  cos(phi_d)
    float* sp_sh    = cp_sh + 16;            // 16  sin(phi_d)
    float* sc_sh    = sp_sh + 16;            // 32
    float* bi_sh    = sc_sh + 32;            // 32
    float* kb_sh    = bi_sh + 32;            // 64
    __shared__ int flag_sh;                  // 1 if cand0 is sum_scale

    const int t  = threadIdx.x;
    const int b0 = blockIdx.x * TB;
    const float CLIPF = (float)(1.0 - 1e-6);

    // ---- disambiguate sum_scale (mean ~1) vs sum_bias (mean ~0) by data ----
    if (t == 0) {
        float s0 = 0.f, s1 = 0.f;
        for (int i = 0; i < 32; i++) { s0 += cand0[i]; s1 += cand1[i]; }
        flag_sh = (s0 > s1) ? 1 : 0;
    }
    __syncthreads();

    // ---- staging ----
    for (int j = t; j < DEG * FEAT; j += 256) {       // lcu_w [f][d] -> wT [d][f]
        const int f = j >> 4, d = j & 15;
        wT_sh[d * 32 + f] = lcu_w[j];
    }
    if (t < 32) {
        float denom = 1e-6f;
#pragma unroll
        for (int d = 0; d < DEG; d++) denom += fabsf(lcu_w[t * DEG + d]);
        inv_sh[t] = 1.0f / denom;
        sc_sh[t] = flag_sh ? cand0[t] : cand1[t];
        bi_sh[t] = flag_sh ? cand1[t] : cand0[t];
    }
    if (t < 16) {
        float sv, cv;
        sincosf(phases[t], &sv, &cv);
        cp_sh[t] = cv;
        sp_sh[t] = sv;
    }
    if (t < 64) kb_sh[t] = kan_bias[t];
    // kan_coeff global [c][f][k] -> shared [f][k][c]
    for (int j = t; j < CLS * FEAT * GRIDK; j += 256) {
        const int c   = j >> 8;
        const int rem = j & 255;                      // f*8 + k
        coeff_sh[rem * 64 + c] = kan_coeff[j];
    }
    __syncthreads();

    // ---- Phase A: QSVT+LCU+tanh. cos(k*th+phi) = c_k*cos(phi) - s_k*sin(phi),
    //      (c_k, s_k) by exact angle-addition from c1=x, s1=sqrt(1-x^2). ----
    {
        const int f  = t & 31;
        const int w8 = t >> 5;
        const float invd = inv_sh[f];
        const float sc = sc_sh[f];
        const float bi = bi_sh[f];
        for (int i = 0; i < TB / 8; i++) {
            const int r = w8 + 8 * i;
            float x = X[(size_t)(b0 + r) * FEAT + f];
            x = fminf(fmaxf(x, -CLIPF), CLIPF);
            const float sn = sqrtf(fmaf(-x, x, 1.0f));   // sin(theta) > 0
            float c = x, s = sn, num = 0.f;              // cos(1*th), sin(1*th)
#pragma unroll
            for (int d = 0; d < DEG; d++) {
                const float q = fmaf(c, cp_sh[d], -(s * sp_sh[d]));  // cos(k*th+phi_d)
                num = fmaf(wT_sh[d * 32 + f], q, num);
                const float cn = fmaf(-sn, s, c * x);
                s = fmaf(sn, c, s * x);
                c = cn;
            }
            float y = tanhf(fmaf(sc, num * invd, bi));
            y_sh[f * YSTR + r] = fminf(fmaxf(y, -CLIPF), CLIPF);
        }
    }
    __syncthreads();

    // ---- Phase B: Chebyshev basis (T_k(y) = cos(k*acos y)) + f32x2 GEMM ----
    // Thread tile: 2 batch rows x 32 classes (16 class-pairs per row).
    {
        const int ch = t >> 7;          // 0..1 -> classes ch*32..+31
        const int rw = t & 127;         // 0..127 -> rows 2*rw, 2*rw+1
        const int c0 = ch * 32;

        unsigned long long acc0[16], acc1[16];
#pragma unroll
        for (int j = 0; j < 16; j++) { acc0[j] = 0ull; acc1[j] = 0ull; }

        for (int f = 0; f < FEAT; f++) {
            const float2 yy = *(const float2*)&y_sh[f * YSTR + 2 * rw];
            float T0[GRIDK], T1[GRIDK];
            T0[0] = 1.0f; T0[1] = yy.x;
            T1[0] = 1.0f; T1[1] = yy.y;
            const float y20 = yy.x + yy.x;
            const float y21 = yy.y + yy.y;
#pragma unroll
            for (int k = 2; k < GRIDK; k++) {
                T0[k] = fmaf(y20, T0[k - 1], -T0[k - 2]);
                T1[k] = fmaf(y21, T1[k - 1], -T1[k - 2]);
            }
            const float* base = coeff_sh + f * (GRIDK * CLS) + c0;
#pragma unroll
            for (int k = 0; k < GRIDK; k++) {
                const ulonglong2* qp = (const ulonglong2*)(base + k * CLS);
                const ulonglong2 q0 = qp[0];
                const ulonglong2 q1 = qp[1];
                const ulonglong2 q2 = qp[2];
                const ulonglong2 q3 = qp[3];
                const ulonglong2 q4 = qp[4];
                const ulonglong2 q5 = qp[5];
                const ulonglong2 q6 = qp[6];
                const ulonglong2 q7 = qp[7];
                const unsigned long long tp0 = pack2(T0[k]);
                const unsigned long long tp1 = pack2(T1[k]);
                acc0[0]  = fma2(tp0, q0.x, acc0[0]);   acc1[0]  = fma2(tp1, q0.x, acc1[0]);
                acc0[1]  = fma2(tp0, q0.y, acc0[1]);   acc1[1]  = fma2(tp1, q0.y, acc1[1]);
                acc0[2]  = fma2(tp0, q1.x, acc0[2]);   acc1[2]  = fma2(tp1, q1.x, acc1[2]);
                acc0[3]  = fma2(tp0, q1.y, acc0[3]);   acc1[3]  = fma2(tp1, q1.y, acc1[3]);
                acc0[4]  = fma2(tp0, q2.x, acc0[4]);   acc1[4]  = fma2(tp1, q2.x, acc1[4]);
                acc0[5]  = fma2(tp0, q2.y, acc0[5]);   acc1[5]  = fma2(tp1, q2.y, acc1[5]);
                acc0[6]  = fma2(tp0, q3.x, acc0[6]);   acc1[6]  = fma2(tp1, q3.x, acc1[6]);
                acc0[7]  = fma2(tp0, q3.y, acc0[7]);   acc1[7]  = fma2(tp1, q3.y, acc1[7]);
                acc0[8]  = fma2(tp0, q4.x, acc0[8]);   acc1[8]  = fma2(tp1, q4.x, acc1[8]);
                acc0[9]  = fma2(tp0, q4.y, acc0[9]);   acc1[9]  = fma2(tp1, q4.y, acc1[9]);
                acc0[10] = fma2(tp0, q5.x, acc0[10]);  acc1[10] = fma2(tp1, q5.x, acc1[10]);
                acc0[11] = fma2(tp0, q5.y, acc0[11]);  acc1[11] = fma2(tp1, q5.y, acc1[11]);
                acc0[12] = fma2(tp0, q6.x, acc0[12]);  acc1[12] = fma2(tp1, q6.x, acc1[12]);
                acc0[13] = fma2(tp0, q6.y, acc0[13]);  acc1[13] = fma2(tp1, q6.y, acc1[13]);
                acc0[14] = fma2(tp0, q7.x, acc0[14]);  acc1[14] = fma2(tp1, q7.x, acc1[14]);
                acc0[15] = fma2(tp0, q7.y, acc0[15]);  acc1[15] = fma2(tp1, q7.y, acc1[15]);
            }
        }

        // ---- epilogue: + kan_bias, 16B stores ----
        const unsigned long long* kbp = (const unsigned long long*)(kb_sh + c0);
        unsigned long long bp[16];
#pragma unroll
        for (int j = 0; j < 16; j++) bp[j] = kbp[j];

        const size_t r0 = (size_t)(b0 + 2 * rw);
        ulonglong2* op0 = (ulonglong2*)(out + r0 * CLS + c0);
        ulonglong2* op1 = (ulonglong2*)(out + (r0 + 1) * CLS + c0);
#pragma unroll
        for (int j = 0; j < 8; j++) {
            ulonglong2 v0, v1;
            v0.x = add2(acc0[2 * j],     bp[2 * j]);
            v0.y = add2(acc0[2 * j + 1], bp[2 * j + 1]);
            v1.x = add2(acc1[2 * j],     bp[2 * j]);
            v1.y = add2(acc1[2 * j + 1], bp[2 * j + 1]);
            op0[j] = v0;
            op1[j] = v1;
        }
    }
}

extern "C" void kernel_launch(void* const* d_in, const int* in_sizes, int n_in,
                              void* d_out, int out_size) {
    // Identify inputs by element count; the two 32-vectors are disambiguated
    // in-kernel by their means (scale ~1, bias ~0).
    int iX = 0, iP = 1, iW = 2, iC = 5, iKB = 6;
    int i32[2] = {3, 4};
    int n32 = 0;
    for (int i = 0; i < n_in; i++) {
        switch (in_sizes[i]) {
            case 4194304: iX = i; break;
            case 16:      iP = i; break;
            case 512:     iW = i; break;
            case 16384:   iC = i; break;
            case 64:      iKB = i; break;
            case 32:      if (n32 < 2) i32[n32] = i; n32++; break;
            default: break;
        }
    }

    const float* X      = (const float*)d_in[iX];
    const float* phases = (const float*)d_in[iP];
    const float* w      = (const float*)d_in[iW];
    const float* cand0  = (const float*)d_in[i32[0]];
    const float* cand1  = (const float*)d_in[i32[1]];
    const float* coeff  = (const float*)d_in[iC];
    const float* kbias  = (const float*)d_in[iKB];
    float* out          = (float*)d_out;

    const size_t smem_bytes =
        (16384 + 32 * YSTR + 512 + 32 + 16 + 16 + 32 + 32 + 64) * sizeof(float); // 101376 B
    cudaFuncSetAttribute(qkan_kernel, cudaFuncAttributeMaxDynamicSharedMemorySize,
                         (int)smem_bytes);

    qkan_kernel<<<BATCH / TB, 256, smem_bytes>>>(X, phases, w, cand0, cand1,
                                                 coeff, kbias, out);
}

// round 7
// speedup vs baseline: 3.6550x; 1.7439x over previous
#include <cuda_runtime.h>
#include <cuda_bf16.h>
#include <cstdint>

#define BATCH  131072
#define FEAT   32
#define DEG    16
#define CLS    64
#define GRIDK  8
#define TBROWS 128          // rows per block
#define NKT    16           // K=256 / 16 per MMA

// ---- dynamic smem byte offsets ----
#define OFF_FLAG    0
#define OFF_PAR     64                        // float params
#define PAR_WT      0                         // [d][f] 512 floats
#define PAR_INV     512
#define PAR_CP      544
#define PAR_SP      560
#define PAR_SC      576
#define PAR_BI      608
#define PAR_KB      640                       // 64 floats
#define OFF_A_HI    4096                      // [128][256] bf16, 512B rows, chunk^row swizzle
#define OFF_A_LO    (OFF_A_HI + 65536)
#define OFF_B_HI    (OFF_A_LO + 65536)        // [64][256] bf16
#define OFF_B_LO    (OFF_B_HI + 32768)
#define SMEM_TOTAL  (OFF_B_LO + 32768)        // 200704 B

static __device__ __forceinline__ uint32_t smem_u32(const void* p) {
    uint32_t a;
    asm("{ .reg .u64 t; cvta.to.shared.u64 t, %1; cvt.u32.u64 %0, t; }" : "=r"(a) : "l"(p));
    return a;
}
static __device__ __forceinline__ void ldsm4(uint32_t& r0, uint32_t& r1, uint32_t& r2,
                                             uint32_t& r3, uint32_t addr) {
    asm volatile("ldmatrix.sync.aligned.m8n8.x4.shared.b16 {%0,%1,%2,%3}, [%4];"
                 : "=r"(r0), "=r"(r1), "=r"(r2), "=r"(r3) : "r"(addr));
}
static __device__ __forceinline__ void mma_bf16(float* c, const uint32_t* a,
                                                const uint32_t* b) {
    asm volatile("mma.sync.aligned.m16n8k16.row.col.f32.bf16.bf16.f32 "
                 "{%0,%1,%2,%3}, {%4,%5,%6,%7}, {%8,%9}, {%0,%1,%2,%3};"
                 : "+f"(c[0]), "+f"(c[1]), "+f"(c[2]), "+f"(c[3])
                 : "r"(a[0]), "r"(a[1]), "r"(a[2]), "r"(a[3]), "r"(b[0]), "r"(b[1]));
}
static __device__ __forceinline__ uint32_t pack_bf2(float a, float b) {
    __nv_bfloat162 h = __floats2bfloat162_rn(a, b);
    return *reinterpret_cast<uint32_t*>(&h);
}

__global__ __launch_bounds__(256)
void qkan_mma_kernel(const float* __restrict__ X,
                     const float* __restrict__ phases,
                     const float* __restrict__ lcu_w,
                     const float* __restrict__ cand0,
                     const float* __restrict__ cand1,
                     const float* __restrict__ kan_coeff,
                     const float* __restrict__ kan_bias,
                     float* __restrict__ out) {
    extern __shared__ char smc[];
    float* par = (float*)(smc + OFF_PAR);

    const int t    = threadIdx.x;
    const int wid  = t >> 5;
    const int lane = t & 31;
    const int row0 = blockIdx.x * TBROWS;
    const uint32_t smem_base = smem_u32(smc);
    const float CLIPF = (float)(1.0 - 1e-6);

    // ---- scale/bias disambiguation (scale mean ~1 > bias mean ~0) ----
    if (t == 0) {
        float s0 = 0.f, s1 = 0.f;
        for (int i = 0; i < 32; i++) { s0 += cand0[i]; s1 += cand1[i]; }
        *(int*)(smc + OFF_FLAG) = (s0 > s1) ? 1 : 0;
    }
    __syncthreads();
    const int flag = *(const int*)(smc + OFF_FLAG);

    // ---- parameter staging ----
    for (int j = t; j < DEG * FEAT; j += 256) {        // lcu_w [f][d] -> wT [d][f]
        const int f = j >> 4, d = j & 15;
        par[PAR_WT + d * 32 + f] = lcu_w[j];
    }
    if (t < 32) {
        float denom = 1e-6f;
#pragma unroll
        for (int d = 0; d < DEG; d++) denom += fabsf(lcu_w[t * DEG + d]);
        par[PAR_INV + t] = 1.0f / denom;
        par[PAR_SC + t] = flag ? cand0[t] : cand1[t];
        par[PAR_BI + t] = flag ? cand1[t] : cand0[t];
    }
    if (t < 16) {
        float sv, cv;
        sincosf(phases[t], &sv, &cv);
        par[PAR_CP + t] = cv;
        par[PAR_SP + t] = sv;
    }
    if (t < 64) par[PAR_KB + t] = kan_bias[t];

    // ---- B tiles: kan_coeff [c][256] -> bf16 hi/lo, 512B rows, chunk^(c&7) swizzle ----
#pragma unroll
    for (int it = 0; it < 8; it++) {
        const int j = t + 256 * it;          // chunk id: 2048 chunks of 8 floats
        const int c = j >> 5;                // class row 0..63
        const int q = j & 31;                // 16B chunk within row
        const float4* gp = (const float4*)(kan_coeff + c * 256 + q * 8);
        const float4 v0 = gp[0];
        const float4 v1 = gp[1];
        float v[8] = {v0.x, v0.y, v0.z, v0.w, v1.x, v1.y, v1.z, v1.w};
        uint32_t hi[4], lo[4];
#pragma unroll
        for (int k = 0; k < 4; k++) {
            const __nv_bfloat16 h0 = __float2bfloat16_rn(v[2 * k]);
            const __nv_bfloat16 h1 = __float2bfloat16_rn(v[2 * k + 1]);
            const float l0 = v[2 * k]     - __bfloat162float(h0);
            const float l1 = v[2 * k + 1] - __bfloat162float(h1);
            __nv_bfloat162 hh; hh.x = h0; hh.y = h1;
            hi[k] = *reinterpret_cast<uint32_t*>(&hh);
            lo[k] = pack_bf2(l0, l1);
        }
        const uint32_t off = (uint32_t)(c * 512 + ((q ^ (c & 7)) << 4));
        *(uint4*)(smc + OFF_B_HI + off) = make_uint4(hi[0], hi[1], hi[2], hi[3]);
        *(uint4*)(smc + OFF_B_LO + off) = make_uint4(lo[0], lo[1], lo[2], lo[3]);
    }

    // ---- stage 1 (verified R4 math) + Chebyshev basis -> A hi/lo bf16 tiles ----
    {
        const int f  = lane;
        const int w8 = wid;
        const float invd = par[PAR_INV + f];
        const float sc   = par[PAR_SC + f];
        const float bi   = par[PAR_BI + f];
#pragma unroll 2
        for (int i = 0; i < TBROWS / 8; i++) {
            const int r = w8 + 8 * i;
            float x = X[(size_t)(row0 + r) * FEAT + f];
            x = fminf(fmaxf(x, -CLIPF), CLIPF);
            const float sn = sqrtf(fmaf(-x, x, 1.0f));
            float c = x, s = sn, num = 0.f;
#pragma unroll
            for (int d = 0; d < DEG; d++) {
                const float q = fmaf(c, par[PAR_CP + d], -(s * par[PAR_SP + d]));
                num = fmaf(par[PAR_WT + d * 32 + f], q, num);
                const float cn = fmaf(-sn, s, c * x);
                s = fmaf(sn, c, s * x);
                c = cn;
            }
            float y = tanhf(fmaf(sc, num * invd, bi));
            y = fminf(fmaxf(y, -CLIPF), CLIPF);

            float T[GRIDK];
            T[0] = 1.0f; T[1] = y;
            const float y2 = y + y;
#pragma unroll
            for (int k = 2; k < GRIDK; k++) T[k] = fmaf(y2, T[k - 1], -T[k - 2]);

            uint32_t hi[4], lo[4];
#pragma unroll
            for (int k = 0; k < 4; k++) {
                const __nv_bfloat16 h0 = __float2bfloat16_rn(T[2 * k]);
                const __nv_bfloat16 h1 = __float2bfloat16_rn(T[2 * k + 1]);
                const float l0 = T[2 * k]     - __bfloat162float(h0);
                const float l1 = T[2 * k + 1] - __bfloat162float(h1);
                __nv_bfloat162 hh; hh.x = h0; hh.y = h1;
                hi[k] = *reinterpret_cast<uint32_t*>(&hh);
                lo[k] = pack_bf2(l0, l1);
            }
            // row r, K-chunk = f (8 bf16 = 16B), swizzle chunk ^ (r&7)
            const uint32_t off = (uint32_t)(r * 512 + ((f ^ (r & 7)) << 4));
            *(uint4*)(smc + OFF_A_HI + off) = make_uint4(hi[0], hi[1], hi[2], hi[3]);
            *(uint4*)(smc + OFF_A_LO + off) = make_uint4(lo[0], lo[1], lo[2], lo[3]);
        }
    }
    __syncthreads();

    // ---- MMA phase: warp w -> rows w*16..+15, 64 classes, K=256, 3 hi/lo passes ----
    {
        const int lr = lane & 7;
        const int a_cb = (lane >> 4) & 1;                       // A k-subchunk select
        const int arow = wid * 16 + ((lane >> 3) & 1) * 8 + lr; // A row for this lane
        const int b_cb = (lane >> 3) & 1;                       // B k-subchunk select
        const int bn   = ((lane >> 4) & 1) * 8 + lr;            // B n-row within pair

        const uint32_t aBaseHi = smem_base + OFF_A_HI + arow * 512;
        const uint32_t aBaseLo = smem_base + OFF_A_LO + arow * 512;
        uint32_t bBaseHi[4];
#pragma unroll
        for (int p = 0; p < 4; p++)
            bBaseHi[p] = smem_base + OFF_B_HI + (p * 16 + bn) * 512;

        float C[8][4];
#pragma unroll
        for (int n = 0; n < 8; n++)
#pragma unroll
            for (int j = 0; j < 4; j++) C[n][j] = 0.f;

#pragma unroll
        for (int kt = 0; kt < NKT; kt++) {
            const uint32_t offA = (uint32_t)(((kt * 2 + a_cb) ^ lr) << 4);
            const uint32_t offB = (uint32_t)(((kt * 2 + b_cb) ^ lr) << 4);
            uint32_t ah[4], al[4];
            ldsm4(ah[0], ah[1], ah[2], ah[3], aBaseHi + offA);
            ldsm4(al[0], al[1], al[2], al[3], aBaseLo + offA);
            uint32_t bh[8][2], bl[8][2];
#pragma unroll
            for (int p = 0; p < 4; p++) {
                ldsm4(bh[2 * p][0], bh[2 * p][1], bh[2 * p + 1][0], bh[2 * p + 1][1],
                      bBaseHi[p] + offB);
                ldsm4(bl[2 * p][0], bl[2 * p][1], bl[2 * p + 1][0], bl[2 * p + 1][1],
                      bBaseHi[p] + 32768u + offB);
            }
#pragma unroll
            for (int n = 0; n < 8; n++) {
                mma_bf16(C[n], ah, bh[n]);
                mma_bf16(C[n], al, bh[n]);
                mma_bf16(C[n], ah, bl[n]);
            }
        }

        // ---- epilogue: + kan_bias, float2 stores ----
        const int qrow = lane >> 2;            // 0..7
        const int col2 = 2 * (lane & 3);       // 0,2,4,6
        const int gr0 = row0 + wid * 16 + qrow;
#pragma unroll
        for (int n = 0; n < 8; n++) {
            const int col = n * 8 + col2;
            const float kb0 = par[PAR_KB + col];
            const float kb1 = par[PAR_KB + col + 1];
            float2 v0, v1;
            v0.x = C[n][0] + kb0; v0.y = C[n][1] + kb1;
            v1.x = C[n][2] + kb0; v1.y = C[n][3] + kb1;
            *(float2*)(out + (size_t)gr0 * CLS + col) = v0;
            *(float2*)(out + (size_t)(gr0 + 8) * CLS + col) = v1;
        }
    }
}

extern "C" void kernel_launch(void* const* d_in, const int* in_sizes, int n_in,
                              void* d_out, int out_size) {
    int iX = 0, iP = 1, iW = 2, iC = 5, iKB = 6;
    int i32[2] = {3, 4};
    int n32 = 0;
    for (int i = 0; i < n_in; i++) {
        switch (in_sizes[i]) {
            case 4194304: iX = i; break;
            case 16:      iP = i; break;
            case 512:     iW = i; break;
            case 16384:   iC = i; break;
            case 64:      iKB = i; break;
            case 32:      if (n32 < 2) i32[n32] = i; n32++; break;
            default: break;
        }
    }

    const float* X      = (const float*)d_in[iX];
    const float* phases = (const float*)d_in[iP];
    const float* w      = (const float*)d_in[iW];
    const float* cand0  = (const float*)d_in[i32[0]];
    const float* cand1  = (const float*)d_in[i32[1]];
    const float* coeff  = (const float*)d_in[iC];
    const float* kbias  = (const float*)d_in[iKB];
    float* out          = (float*)d_out;

    cudaFuncSetAttribute(qkan_mma_kernel, cudaFuncAttributeMaxDynamicSharedMemorySize,
                         SMEM_TOTAL);
    qkan_mma_kernel<<<BATCH / TBROWS, 256, SMEM_TOTAL>>>(X, phases, w, cand0, cand1,
                                                         coeff, kbias, out);
}